// round 13
// baseline (speedup 1.0000x reference)
#include <cuda_runtime.h>

#define BATCH 524288u
#define TPB 256
#define GRID 740u            // 148 SMs, single wave
#define STRIDE (GRID * TPB)  // 189440
typedef unsigned long long u64;

// ---- packed f32x2 primitives ----
#define F2MUL(d,a,b)    asm("mul.rn.f32x2 %0, %1, %2;" : "=l"(d) : "l"(a), "l"(b))
#define F2ADD(d,a,b)    asm("add.rn.f32x2 %0, %1, %2;" : "=l"(d) : "l"(a), "l"(b))
#define F2FMA(d,a,b,c)  asm("fma.rn.f32x2 %0, %1, %2, %3;" : "=l"(d) : "l"(a), "l"(b), "l"(c))
#define F2PACK(d,lo,hi) asm("mov.b64 %0, {%1, %2};" : "=l"(d) : "f"(lo), "f"(hi))
#define F2UNPACK(lo,hi,s) asm("mov.b64 {%0, %1}, %2;" : "=f"(lo), "=f"(hi) : "l"(s))
#define F2SWAP(d,s) asm("{\n\t.reg .b32 _l,_h;\n\tmov.b64 {_l,_h}, %1;\n\tmov.b64 %0, {_h,_l};\n\t}" : "=l"(d) : "l"(s))

#define SGNBOTH 0x8000000080000000ULL

__device__ __forceinline__ float2 cmul(float2 a, float2 b) {
    return make_float2(fmaf(a.x, b.x, -a.y * b.y), fmaf(a.x, b.y, a.y * b.x));
}

// lane-aligned RY on pack pair: A' = c*A + sA*B ; B' = c*B + sB*oldA
__device__ __forceinline__ void ry_al(u64& AR, u64& AI, u64& BR, u64& BI,
                                      u64 c2, u64 sA, u64 sB) {
    u64 t1, t2, t3, t4, oAR = AR, oAI = AI;
    F2MUL(t1, c2, AR); F2MUL(t2, c2, AI); F2MUL(t3, c2, BR); F2MUL(t4, c2, BI);
    F2FMA(AR, sA, BR, t1);
    F2FMA(AI, sA, BI, t2);
    F2FMA(BR, sB, oAR, t3);
    F2FMA(BI, sB, oAI, t4);
}

// full circuit for one sample (VERIFIED R10 path) — used only as the per-block
// oracle at the 81 interpolation grid points.
__device__ __forceinline__ float4 qbody(
    float4 xv, const float4* __restrict__ l0c,
    const ulonglong2* __restrict__ dRIp,
    const float4* __restrict__ r0c4, const float4* __restrict__ r1c4,
    const float4* __restrict__ r2c4, const float* __restrict__ w3c)
{
    const u64 NEG1 = 0xBF800000BF800000ULL;
    float xs[4] = {xv.x, xv.y, xv.z, xv.w};

    float2 u0[4], u1[4];
    #pragma unroll
    for (int q = 0; q < 4; q++) {
        float4 cc = l0c[q];
        float sx, cx;
        __sincosf(0.5f * xs[q], &sx, &cx);
        float t  = sx * cc.z;
        float qq = sx * cc.w;
        float m1 = cc.y * t;
        u0[q].x = fmaf(cc.x, cx, -m1);
        u0[q].y = -(cc.y * qq);
        u1[q].x = fmaf(cc.y, cx, cc.x * t);
        u1[q].y = cc.x * qq;
    }
    float2 a01[4], a23[4];
    a01[0] = cmul(u0[0], u0[1]); a01[1] = cmul(u0[0], u1[1]);
    a01[2] = cmul(u1[0], u0[1]); a01[3] = cmul(u1[0], u1[1]);
    a23[0] = cmul(u0[2], u0[3]); a23[1] = cmul(u0[2], u1[3]);
    a23[2] = cmul(u1[2], u0[3]); a23[3] = cmul(u1[2], u1[3]);

    u64 A0R, A0I, A1R, A1I;
    F2PACK(A0R, a01[0].x, a01[3].x); F2PACK(A0I, a01[0].y, a01[3].y);
    F2PACK(A1R, a01[1].x, a01[2].x); F2PACK(A1I, a01[1].y, a01[2].y);
    u64 sR[8], sI[8];
    #pragma unroll
    for (int j = 0; j < 4; j++) {
        u64 BR, BI, nBI, t;
        F2PACK(BR, a23[j].x, a23[j].x);
        F2PACK(BI, a23[j].y, a23[j].y);
        nBI = BI ^ SGNBOTH;
        F2MUL(t, A0R, BR); F2FMA(sR[j],     A0I, nBI, t);
        F2MUL(t, A0R, BI); F2FMA(sI[j],     A0I, BR,  t);
        F2MUL(t, A1R, BR); F2FMA(sR[4 + j], A1I, nBI, t);
        F2MUL(t, A1R, BI); F2FMA(sI[4 + j], A1I, BR,  t);
    }
    #pragma unroll
    for (int p = 0; p < 8; p++) {
        ulonglong2 dv = dRIp[p];
        u64 cR = dv.x, cI = dv.y, ncI = cI ^ SGNBOTH;
        u64 t1, t2, oR = sR[p];
        F2MUL(t1, cR, sR[p]); F2MUL(t2, cR, sI[p]);
        F2FMA(sR[p], ncI, sI[p], t1);
        F2FMA(sI[p], cI,  oR,    t2);
    }
    {
        ulonglong2 rv = *reinterpret_cast<const ulonglong2*>(r0c4);
        u64 c0 = rv.x, svE = rv.y, svO = svE ^ SGNBOTH;
        #pragma unroll
        for (int p = 0; p < 8; p++) {
            u64 sv = (p == 0 || p == 3 || p == 5 || p == 6) ? svE : svO;
            u64 wR, wI, t1, t2;
            F2SWAP(wR, sR[p]); F2SWAP(wI, sI[p]);
            F2MUL(t1, c0, sR[p]); F2MUL(t2, c0, sI[p]);
            F2FMA(sR[p], sv, wR, t1);
            F2FMA(sI[p], sv, wI, t2);
        }
    }
    {
        ulonglong2 rv = *reinterpret_cast<const ulonglong2*>(r1c4);
        u64 c = rv.x, sA = rv.y, sB = sA ^ SGNBOTH;
        ry_al(sR[0], sI[0], sR[6], sI[6], c, sA, sB);
        ry_al(sR[1], sI[1], sR[7], sI[7], c, sA, sB);
        ry_al(sR[2], sI[2], sR[4], sI[4], c, sA, sB);
        ry_al(sR[3], sI[3], sR[5], sI[5], c, sA, sB);
    }
    {
        ulonglong2 rv = *reinterpret_cast<const ulonglong2*>(r2c4);
        u64 c = rv.x, sA = rv.y, sB = sA ^ SGNBOTH;
        ry_al(sR[0], sI[0], sR[3], sI[3], c, sA, sB);
        ry_al(sR[1], sI[1], sR[2], sI[2], c, sA, sB);
        ry_al(sR[7], sI[7], sR[4], sI[4], c, sA, sB);
        ry_al(sR[6], sI[6], sR[5], sI[5], c, sA, sB);
    }
    u64 P[8];
    #pragma unroll
    for (int p = 0; p < 8; p++) {
        u64 t; F2MUL(t, sR[p], sR[p]); F2FMA(P[p], sI[p], sI[p], t);
    }
    u64 CR[4];
    #pragma unroll
    for (int i = 0; i < 4; i++) {
        int p = 2 * i;
        u64 wr, wi, t;
        F2SWAP(wr, sR[p + 1]); F2SWAP(wi, sI[p + 1]);
        F2MUL(t, sR[p], wr); F2FMA(CR[i], sI[p], wi, t);
    }
    u64 sm[4], df[4];
    #pragma unroll
    for (int i = 0; i < 4; i++) {
        F2ADD(sm[i], P[2 * i], P[2 * i + 1]);
        F2FMA(df[i], P[2 * i + 1], NEG1, P[2 * i]);
    }
    u64 t1, t2, Ea, Eb, Ec, Up, Vd, g1, g2;
    F2ADD(t1, df[0], df[1]); F2ADD(t2, df[2], df[3]); F2FMA(Ea, t2, NEG1, t1);
    F2ADD(t1, df[0], df[2]); F2ADD(t2, df[1], df[3]); F2FMA(Eb, t2, NEG1, t1);
    F2ADD(t1, sm[0], sm[2]); F2ADD(t2, sm[1], sm[3]); F2FMA(Ec, t2, NEG1, t1);
    F2FMA(g1, CR[1], NEG1, CR[0]); F2FMA(g2, CR[3], NEG1, CR[2]); F2ADD(Up, g1, g2);
    F2ADD(t1, CR[0], CR[1]); F2ADD(t2, CR[2], CR[3]); F2FMA(Vd, t2, NEG1, t1);

    float eal, eah, ebl, ebh, ecl, ech, upl, uph, vdl, vdh;
    F2UNPACK(eal, eah, Ea); F2UNPACK(ebl, ebh, Eb); F2UNPACK(ecl, ech, Ec);
    F2UNPACK(upl, uph, Up); F2UNPACK(vdl, vdh, Vd);
    float c3 = w3c[0], s3n2 = w3c[1];
    float W13 = eal + eah;
    float W5  = eal - eah;
    float W11 = ebl - ebh;
    float W10 = ecl - ech;
    float C0 = upl + uph;
    float C3 = vdl - vdh;
    float4 o;
    o.x = fmaf(c3, W13, s3n2 * C0);
    o.y = W11;
    o.z = W5;
    o.w = fmaf(c3, W10, s3n2 * C3);
    return o;
}

// per-sample fast path: 4 full-angle sincos + 81-coefficient Horner contraction
__device__ __forceinline__ float4 hbody(float4 xv, const float* __restrict__ kf) {
    float C0, S0, C1, S1, C2, S2, C3, S3;
    __sincosf(xv.x, &S0, &C0);
    __sincosf(xv.y, &S1, &C1);
    __sincosf(xv.z, &S2, &C2);
    __sincosf(xv.w, &S3, &C3);
    u64 wC0, wS0, wC1, wS1, wC2, wS2, wC3, wS3;
    F2PACK(wC0, C0, C0); F2PACK(wS0, S0, S0);
    F2PACK(wC1, C1, C1); F2PACK(wS1, S1, S1);
    F2PACK(wC2, C2, C2); F2PACK(wS2, S2, S2);
    F2PACK(wC3, C3, C3); F2PACK(wS3, S3, S3);

    const ulonglong2* Kp = reinterpret_cast<const ulonglong2*>(kf);
    u64 A1a = 0, A1b = 0;
    #pragma unroll
    for (int t1 = 0; t1 < 3; t1++) {
        u64 A2a = 0, A2b = 0;
        #pragma unroll
        for (int t2 = 0; t2 < 3; t2++) {
            u64 A3a = 0, A3b = 0;
            #pragma unroll
            for (int t3 = 0; t3 < 3; t3++) {
                int ci = ((t1 * 3 + t2) * 3 + t3) * 3;   // 3 x 16B per cell
                ulonglong2 v0 = Kp[ci], v1 = Kp[ci + 1], v2 = Kp[ci + 2];
                u64 ha = v0.x, hb = v0.y;
                F2FMA(ha, wC3, v1.x, ha);
                F2FMA(ha, wS3, v2.x, ha);
                F2FMA(hb, wC3, v1.y, hb);
                F2FMA(hb, wS3, v2.y, hb);
                if (t3 == 0)      { A3a = ha; A3b = hb; }
                else if (t3 == 1) { F2FMA(A3a, wC2, ha, A3a); F2FMA(A3b, wC2, hb, A3b); }
                else              { F2FMA(A3a, wS2, ha, A3a); F2FMA(A3b, wS2, hb, A3b); }
            }
            if (t2 == 0)      { A2a = A3a; A2b = A3b; }
            else if (t2 == 1) { F2FMA(A2a, wC1, A3a, A2a); F2FMA(A2b, wC1, A3b, A2b); }
            else              { F2FMA(A2a, wS1, A3a, A2a); F2FMA(A2b, wS1, A3b, A2b); }
        }
        if (t1 == 0)      { A1a = A2a; A1b = A2b; }
        else if (t1 == 1) { F2FMA(A1a, wC0, A2a, A1a); F2FMA(A1b, wC0, A2b, A1b); }
        else              { F2FMA(A1a, wS0, A2a, A1a); F2FMA(A1b, wS0, A2b, A1b); }
    }
    float o0, o1, o2, o3;
    F2UNPACK(o0, o1, A1a);
    F2UNPACK(o2, o3, A1b);
    return make_float4(o0, o1, o2, o3);
}

__device__ __forceinline__ void xform3(float* kf, int base, int st) {
    float f0 = kf[base], f1 = kf[base + st], f2 = kf[base + 2 * st];
    float a = (f0 + f1 + f2) * 0.3333333333333333f;
    float b = f0 - a;
    float c = (f1 - f2) * 0.5773502691896258f;   // 1/sqrt(3)
    kf[base] = a; kf[base + st] = b; kf[base + 2 * st] = c;
}

__global__ void __launch_bounds__(TPB, 4) quantum_layer_kernel(
    const float4* __restrict__ x, const float* __restrict__ w,
    float4* __restrict__ out)
{
    __shared__ __align__(16) float4 l0c[4];
    __shared__ __align__(16) float4 dRI[8];
    __shared__ __align__(16) float4 r0c4, r1c4, r2c4;
    __shared__ float w3c[2];
    __shared__ __align__(16) float kf[324];   // F-values, then kappa in place

    int tid = threadIdx.x;
    if (tid < 4) {
        float sy, cy, sz, cz;
        __sincosf(0.5f * w[2 * tid + 1], &sy, &cy);
        __sincosf(w[2 * tid], &sz, &cz);
        l0c[tid] = make_float4(cy, sy, cz, sz);
    } else if (tid >= 16 && tid < 32) {
        int k = tid - 16;
        float phi = 0.5f * ( w[8]  * ((__popc(k & 7)  & 1) ? -1.f : 1.f)
                           + w[10] * ((__popc(k & 12) & 1) ? -1.f : 1.f)
                           + w[12] * ((__popc(k & 14) & 1) ? -1.f : 1.f)
                           + w[14] * ((__popc(k & 15) & 1) ? -1.f : 1.f) );
        float sp, cp; __sincosf(phi, &sp, &cp);
        int p = (k < 8) ? k : (k ^ 12);
        int l = (k < 8) ? 0 : 1;
        float* f = reinterpret_cast<float*>(dRI);
        f[4 * p + l]     = cp;
        f[4 * p + 2 + l] = -sp;
    } else if (tid == 32) {
        float s, c; __sincosf(0.5f * w[9], &s, &c);
        r0c4 = make_float4(c, c, -s, s);
    } else if (tid == 33) {
        float s, c; __sincosf(0.5f * w[11], &s, &c);
        r1c4 = make_float4(c, c, -s, -s);
    } else if (tid == 34) {
        float s, c; __sincosf(0.5f * w[13], &s, &c);
        r2c4 = make_float4(c, c, -s, -s);
    } else if (tid == 35) {
        float s, c; __sincosf(w[15], &s, &c);
        w3c[0] = c; w3c[1] = -2.f * s;
    }
    __syncthreads();

    const ulonglong2* dRIp = reinterpret_cast<const ulonglong2*>(dRI);

    // ---- Stage A: evaluate the circuit at the 81 grid points ----
    if (tid < 81) {
        const float TH0 = 0.0f, TH1 = 2.0943951023931953f, TH2 = -2.0943951023931953f;
        int j1 = tid / 27, j2 = (tid / 9) % 3, j3 = (tid / 3) % 3, j4 = tid % 3;
        float th[3] = {TH0, TH1, TH2};
        float4 gx = make_float4(th[j1], th[j2], th[j3], th[j4]);
        float4 r = qbody(gx, l0c, dRIp, &r0c4, &r1c4, &r2c4, w3c);
        kf[tid * 4 + 0] = r.x;
        kf[tid * 4 + 1] = r.y;
        kf[tid * 4 + 2] = r.z;
        kf[tid * 4 + 3] = r.w;
    }
    __syncthreads();

    // ---- Stage B: per-qubit inverse interpolation transforms (in place) ----
    if (tid < 108) { int c = tid >> 2, o = tid & 3; xform3(kf, c * 12 + o, 4); }
    __syncthreads();
    if (tid < 108) { int g = tid / 12, r = tid % 12; xform3(kf, g * 36 + r, 12); }
    __syncthreads();
    if (tid < 108) { int g = tid / 36, r = tid % 36; xform3(kf, g * 108 + r, 36); }
    __syncthreads();
    if (tid < 108) { xform3(kf, tid, 108); }
    __syncthreads();

    // ---- Stage C: exactly 2 uniform iterations + balanced per-block tail ----
    unsigned bid = blockIdx.x;
    unsigned b0 = bid * (unsigned)TPB + tid;
    unsigned b1 = b0 + STRIDE;

    unsigned n = (bid < 368u) ? 197u : 196u;
    unsigned tb = 2u * STRIDE + bid * 196u + min(bid, 368u) + (unsigned)tid;
    bool tact = (unsigned)tid < n;

    float4 xv = x[b0];
    {
        float4 cur = xv;
        xv = x[b1];
        out[b0] = hbody(cur, kf);
    }
    {
        float4 cur = xv;
        if (tact) xv = x[tb];
        out[b1] = hbody(cur, kf);
    }
    if (tact) {
        out[tb] = hbody(xv, kf);
    }
}

extern "C" void kernel_launch(void* const* d_in, const int* in_sizes, int n_in,
                              void* d_out, int out_size) {
    const float4* x = (const float4*)d_in[0];
    const float*  w = (const float*)d_in[1];
    float4* out = (float4*)d_out;
    quantum_layer_kernel<<<GRID, TPB>>>(x, w, out);
}

// round 14
// speedup vs baseline: 1.5863x; 1.5863x over previous
#include <cuda_runtime.h>

#define BATCH 524288u
#define TPB 256
#define GRID 740u            // 148 SMs, single wave
#define STRIDE (GRID * TPB)  // 189440
typedef unsigned long long u64;

// ---- packed f32x2 primitives ----
#define F2MUL(d,a,b)    asm("mul.rn.f32x2 %0, %1, %2;" : "=l"(d) : "l"(a), "l"(b))
#define F2ADD(d,a,b)    asm("add.rn.f32x2 %0, %1, %2;" : "=l"(d) : "l"(a), "l"(b))
#define F2FMA(d,a,b,c)  asm("fma.rn.f32x2 %0, %1, %2, %3;" : "=l"(d) : "l"(a), "l"(b), "l"(c))
#define F2PACK(d,lo,hi) asm("mov.b64 %0, {%1, %2};" : "=l"(d) : "f"(lo), "f"(hi))
#define F2UNPACK(lo,hi,s) asm("mov.b64 {%0, %1}, %2;" : "=f"(lo), "=f"(hi) : "l"(s))
#define F2SWAP(d,s) asm("{\n\t.reg .b32 _l,_h;\n\tmov.b64 {_l,_h}, %1;\n\tmov.b64 %0, {_h,_l};\n\t}" : "=l"(d) : "l"(s))

#define SGNBOTH 0x8000000080000000ULL

__device__ __forceinline__ float2 cmul(float2 a, float2 b) {
    return make_float2(fmaf(a.x, b.x, -a.y * b.y), fmaf(a.x, b.y, a.y * b.x));
}

// lane-aligned RY on pack pair: A' = c*A + sA*B ; B' = c*B + sB*oldA
__device__ __forceinline__ void ry_al(u64& AR, u64& AI, u64& BR, u64& BI,
                                      u64 c2, u64 sA, u64 sB) {
    u64 t1, t2, t3, t4, oAR = AR, oAI = AI;
    F2MUL(t1, c2, AR); F2MUL(t2, c2, AI); F2MUL(t3, c2, BR); F2MUL(t4, c2, BI);
    F2FMA(AR, sA, BR, t1);
    F2FMA(AI, sA, BI, t2);
    F2FMA(BR, sB, oAR, t3);
    F2FMA(BI, sB, oAI, t4);
}

// full circuit for one sample (VERIFIED R10 path) — per-block oracle at the 81
// grid points ONLY. __noinline__ so its register pressure cannot pollute the
// per-sample fast path's allocation (R13's spill storm).
__device__ __noinline__ float4 qbody(
    float4 xv, const float4* __restrict__ l0c,
    const ulonglong2* __restrict__ dRIp,
    const float4* __restrict__ r0c4, const float4* __restrict__ r1c4,
    const float4* __restrict__ r2c4, const float* __restrict__ w3c)
{
    const u64 NEG1 = 0xBF800000BF800000ULL;
    float xs[4] = {xv.x, xv.y, xv.z, xv.w};

    float2 u0[4], u1[4];
    #pragma unroll
    for (int q = 0; q < 4; q++) {
        float4 cc = l0c[q];
        float sx, cx;
        __sincosf(0.5f * xs[q], &sx, &cx);
        float t  = sx * cc.z;
        float qq = sx * cc.w;
        float m1 = cc.y * t;
        u0[q].x = fmaf(cc.x, cx, -m1);
        u0[q].y = -(cc.y * qq);
        u1[q].x = fmaf(cc.y, cx, cc.x * t);
        u1[q].y = cc.x * qq;
    }
    float2 a01[4], a23[4];
    a01[0] = cmul(u0[0], u0[1]); a01[1] = cmul(u0[0], u1[1]);
    a01[2] = cmul(u1[0], u0[1]); a01[3] = cmul(u1[0], u1[1]);
    a23[0] = cmul(u0[2], u0[3]); a23[1] = cmul(u0[2], u1[3]);
    a23[2] = cmul(u1[2], u0[3]); a23[3] = cmul(u1[2], u1[3]);

    u64 A0R, A0I, A1R, A1I;
    F2PACK(A0R, a01[0].x, a01[3].x); F2PACK(A0I, a01[0].y, a01[3].y);
    F2PACK(A1R, a01[1].x, a01[2].x); F2PACK(A1I, a01[1].y, a01[2].y);
    u64 sR[8], sI[8];
    #pragma unroll
    for (int j = 0; j < 4; j++) {
        u64 BR, BI, nBI, t;
        F2PACK(BR, a23[j].x, a23[j].x);
        F2PACK(BI, a23[j].y, a23[j].y);
        nBI = BI ^ SGNBOTH;
        F2MUL(t, A0R, BR); F2FMA(sR[j],     A0I, nBI, t);
        F2MUL(t, A0R, BI); F2FMA(sI[j],     A0I, BR,  t);
        F2MUL(t, A1R, BR); F2FMA(sR[4 + j], A1I, nBI, t);
        F2MUL(t, A1R, BI); F2FMA(sI[4 + j], A1I, BR,  t);
    }
    #pragma unroll
    for (int p = 0; p < 8; p++) {
        ulonglong2 dv = dRIp[p];
        u64 cR = dv.x, cI = dv.y, ncI = cI ^ SGNBOTH;
        u64 t1, t2, oR = sR[p];
        F2MUL(t1, cR, sR[p]); F2MUL(t2, cR, sI[p]);
        F2FMA(sR[p], ncI, sI[p], t1);
        F2FMA(sI[p], cI,  oR,    t2);
    }
    {
        ulonglong2 rv = *reinterpret_cast<const ulonglong2*>(r0c4);
        u64 c0 = rv.x, svE = rv.y, svO = svE ^ SGNBOTH;
        #pragma unroll
        for (int p = 0; p < 8; p++) {
            u64 sv = (p == 0 || p == 3 || p == 5 || p == 6) ? svE : svO;
            u64 wR, wI, t1, t2;
            F2SWAP(wR, sR[p]); F2SWAP(wI, sI[p]);
            F2MUL(t1, c0, sR[p]); F2MUL(t2, c0, sI[p]);
            F2FMA(sR[p], sv, wR, t1);
            F2FMA(sI[p], sv, wI, t2);
        }
    }
    {
        ulonglong2 rv = *reinterpret_cast<const ulonglong2*>(r1c4);
        u64 c = rv.x, sA = rv.y, sB = sA ^ SGNBOTH;
        ry_al(sR[0], sI[0], sR[6], sI[6], c, sA, sB);
        ry_al(sR[1], sI[1], sR[7], sI[7], c, sA, sB);
        ry_al(sR[2], sI[2], sR[4], sI[4], c, sA, sB);
        ry_al(sR[3], sI[3], sR[5], sI[5], c, sA, sB);
    }
    {
        ulonglong2 rv = *reinterpret_cast<const ulonglong2*>(r2c4);
        u64 c = rv.x, sA = rv.y, sB = sA ^ SGNBOTH;
        ry_al(sR[0], sI[0], sR[3], sI[3], c, sA, sB);
        ry_al(sR[1], sI[1], sR[2], sI[2], c, sA, sB);
        ry_al(sR[7], sI[7], sR[4], sI[4], c, sA, sB);
        ry_al(sR[6], sI[6], sR[5], sI[5], c, sA, sB);
    }
    u64 P[8];
    #pragma unroll
    for (int p = 0; p < 8; p++) {
        u64 t; F2MUL(t, sR[p], sR[p]); F2FMA(P[p], sI[p], sI[p], t);
    }
    u64 CR[4];
    #pragma unroll
    for (int i = 0; i < 4; i++) {
        int p = 2 * i;
        u64 wr, wi, t;
        F2SWAP(wr, sR[p + 1]); F2SWAP(wi, sI[p + 1]);
        F2MUL(t, sR[p], wr); F2FMA(CR[i], sI[p], wi, t);
    }
    u64 sm[4], df[4];
    #pragma unroll
    for (int i = 0; i < 4; i++) {
        F2ADD(sm[i], P[2 * i], P[2 * i + 1]);
        F2FMA(df[i], P[2 * i + 1], NEG1, P[2 * i]);
    }
    u64 t1, t2, Ea, Eb, Ec, Up, Vd, g1, g2;
    F2ADD(t1, df[0], df[1]); F2ADD(t2, df[2], df[3]); F2FMA(Ea, t2, NEG1, t1);
    F2ADD(t1, df[0], df[2]); F2ADD(t2, df[1], df[3]); F2FMA(Eb, t2, NEG1, t1);
    F2ADD(t1, sm[0], sm[2]); F2ADD(t2, sm[1], sm[3]); F2FMA(Ec, t2, NEG1, t1);
    F2FMA(g1, CR[1], NEG1, CR[0]); F2FMA(g2, CR[3], NEG1, CR[2]); F2ADD(Up, g1, g2);
    F2ADD(t1, CR[0], CR[1]); F2ADD(t2, CR[2], CR[3]); F2FMA(Vd, t2, NEG1, t1);

    float eal, eah, ebl, ebh, ecl, ech, upl, uph, vdl, vdh;
    F2UNPACK(eal, eah, Ea); F2UNPACK(ebl, ebh, Eb); F2UNPACK(ecl, ech, Ec);
    F2UNPACK(upl, uph, Up); F2UNPACK(vdl, vdh, Vd);
    float c3 = w3c[0], s3n2 = w3c[1];
    float W13 = eal + eah;
    float W5  = eal - eah;
    float W11 = ebl - ebh;
    float W10 = ecl - ech;
    float C0 = upl + uph;
    float C3 = vdl - vdh;
    float4 o;
    o.x = fmaf(c3, W13, s3n2 * C0);
    o.y = W11;
    o.z = W5;
    o.w = fmaf(c3, W10, s3n2 * C3);
    return o;
}

// per-sample fast path: 4 full-angle sincos + 81-coefficient Horner contraction
__device__ __forceinline__ float4 hbody(float4 xv, const float* __restrict__ kf) {
    float C0, S0, C1, S1, C2, S2, C3, S3;
    __sincosf(xv.x, &S0, &C0);
    __sincosf(xv.y, &S1, &C1);
    __sincosf(xv.z, &S2, &C2);
    __sincosf(xv.w, &S3, &C3);
    u64 wC0, wS0, wC1, wS1, wC2, wS2, wC3, wS3;
    F2PACK(wC0, C0, C0); F2PACK(wS0, S0, S0);
    F2PACK(wC1, C1, C1); F2PACK(wS1, S1, S1);
    F2PACK(wC2, C2, C2); F2PACK(wS2, S2, S2);
    F2PACK(wC3, C3, C3); F2PACK(wS3, S3, S3);

    const ulonglong2* Kp = reinterpret_cast<const ulonglong2*>(kf);
    u64 A1a = 0, A1b = 0;
    #pragma unroll
    for (int t1 = 0; t1 < 3; t1++) {
        u64 A2a = 0, A2b = 0;
        #pragma unroll
        for (int t2 = 0; t2 < 3; t2++) {
            u64 A3a = 0, A3b = 0;
            #pragma unroll
            for (int t3 = 0; t3 < 3; t3++) {
                int ci = ((t1 * 3 + t2) * 3 + t3) * 3;   // 3 x 16B per cell
                ulonglong2 v0 = Kp[ci], v1 = Kp[ci + 1], v2 = Kp[ci + 2];
                u64 ha = v0.x, hb = v0.y;
                F2FMA(ha, wC3, v1.x, ha);
                F2FMA(ha, wS3, v2.x, ha);
                F2FMA(hb, wC3, v1.y, hb);
                F2FMA(hb, wS3, v2.y, hb);
                if (t3 == 0)      { A3a = ha; A3b = hb; }
                else if (t3 == 1) { F2FMA(A3a, wC2, ha, A3a); F2FMA(A3b, wC2, hb, A3b); }
                else              { F2FMA(A3a, wS2, ha, A3a); F2FMA(A3b, wS2, hb, A3b); }
            }
            if (t2 == 0)      { A2a = A3a; A2b = A3b; }
            else if (t2 == 1) { F2FMA(A2a, wC1, A3a, A2a); F2FMA(A2b, wC1, A3b, A2b); }
            else              { F2FMA(A2a, wS1, A3a, A2a); F2FMA(A2b, wS1, A3b, A2b); }
        }
        if (t1 == 0)      { A1a = A2a; A1b = A2b; }
        else if (t1 == 1) { F2FMA(A1a, wC0, A2a, A1a); F2FMA(A1b, wC0, A2b, A1b); }
        else              { F2FMA(A1a, wS0, A2a, A1a); F2FMA(A1b, wS0, A2b, A1b); }
    }
    float o0, o1, o2, o3;
    F2UNPACK(o0, o1, A1a);
    F2UNPACK(o2, o3, A1b);
    return make_float4(o0, o1, o2, o3);
}

__device__ __forceinline__ void xform3(float* kf, int base, int st) {
    float f0 = kf[base], f1 = kf[base + st], f2 = kf[base + 2 * st];
    float a = (f0 + f1 + f2) * 0.3333333333333333f;
    float b = f0 - a;
    float c = (f1 - f2) * 0.5773502691896258f;   // 1/sqrt(3)
    kf[base] = a; kf[base + st] = b; kf[base + 2 * st] = c;
}

__global__ void __launch_bounds__(TPB, 3) quantum_layer_kernel(
    const float4* __restrict__ x, const float* __restrict__ w,
    float4* __restrict__ out)
{
    __shared__ __align__(16) float4 l0c[4];
    __shared__ __align__(16) float4 dRI[8];
    __shared__ __align__(16) float4 r0c4, r1c4, r2c4;
    __shared__ float w3c[2];
    __shared__ __align__(16) float kf[324];   // F-values, then kappa in place

    int tid = threadIdx.x;
    if (tid < 4) {
        float sy, cy, sz, cz;
        __sincosf(0.5f * w[2 * tid + 1], &sy, &cy);
        __sincosf(w[2 * tid], &sz, &cz);
        l0c[tid] = make_float4(cy, sy, cz, sz);
    } else if (tid >= 16 && tid < 32) {
        int k = tid - 16;
        float phi = 0.5f * ( w[8]  * ((__popc(k & 7)  & 1) ? -1.f : 1.f)
                           + w[10] * ((__popc(k & 12) & 1) ? -1.f : 1.f)
                           + w[12] * ((__popc(k & 14) & 1) ? -1.f : 1.f)
                           + w[14] * ((__popc(k & 15) & 1) ? -1.f : 1.f) );
        float sp, cp; __sincosf(phi, &sp, &cp);
        int p = (k < 8) ? k : (k ^ 12);
        int l = (k < 8) ? 0 : 1;
        float* f = reinterpret_cast<float*>(dRI);
        f[4 * p + l]     = cp;
        f[4 * p + 2 + l] = -sp;
    } else if (tid == 32) {
        float s, c; __sincosf(0.5f * w[9], &s, &c);
        r0c4 = make_float4(c, c, -s, s);
    } else if (tid == 33) {
        float s, c; __sincosf(0.5f * w[11], &s, &c);
        r1c4 = make_float4(c, c, -s, -s);
    } else if (tid == 34) {
        float s, c; __sincosf(0.5f * w[13], &s, &c);
        r2c4 = make_float4(c, c, -s, -s);
    } else if (tid == 35) {
        float s, c; __sincosf(w[15], &s, &c);
        w3c[0] = c; w3c[1] = -2.f * s;
    }
    __syncthreads();

    const ulonglong2* dRIp = reinterpret_cast<const ulonglong2*>(dRI);

    // ---- Stage A: evaluate the circuit at the 81 grid points ----
    if (tid < 81) {
        const float TH0 = 0.0f, TH1 = 2.0943951023931953f, TH2 = -2.0943951023931953f;
        int j1 = tid / 27, j2 = (tid / 9) % 3, j3 = (tid / 3) % 3, j4 = tid % 3;
        float th[3] = {TH0, TH1, TH2};
        float4 gx = make_float4(th[j1], th[j2], th[j3], th[j4]);
        float4 r = qbody(gx, l0c, dRIp, &r0c4, &r1c4, &r2c4, w3c);
        kf[tid * 4 + 0] = r.x;
        kf[tid * 4 + 1] = r.y;
        kf[tid * 4 + 2] = r.z;
        kf[tid * 4 + 3] = r.w;
    }
    __syncthreads();

    // ---- Stage B: per-qubit inverse interpolation transforms (in place) ----
    if (tid < 108) { int c = tid >> 2, o = tid & 3; xform3(kf, c * 12 + o, 4); }
    __syncthreads();
    if (tid < 108) { int g = tid / 12, r = tid % 12; xform3(kf, g * 36 + r, 12); }
    __syncthreads();
    if (tid < 108) { int g = tid / 36, r = tid % 36; xform3(kf, g * 108 + r, 36); }
    __syncthreads();
    if (tid < 108) { xform3(kf, tid, 108); }
    __syncthreads();

    // ---- Stage C: exactly 2 uniform iterations + balanced per-block tail ----
    unsigned bid = blockIdx.x;
    unsigned b0 = bid * (unsigned)TPB + tid;
    unsigned b1 = b0 + STRIDE;

    unsigned n = (bid < 368u) ? 197u : 196u;
    unsigned tb = 2u * STRIDE + bid * 196u + min(bid, 368u) + (unsigned)tid;
    bool tact = (unsigned)tid < n;

    float4 xv = x[b0];
    {
        float4 cur = xv;
        xv = x[b1];
        out[b0] = hbody(cur, kf);
    }
    {
        float4 cur = xv;
        if (tact) xv = x[tb];
        out[b1] = hbody(cur, kf);
    }
    if (tact) {
        out[tb] = hbody(xv, kf);
    }
}

extern "C" void kernel_launch(void* const* d_in, const int* in_sizes, int n_in,
                              void* d_out, int out_size) {
    const float4* x = (const float4*)d_in[0];
    const float*  w = (const float*)d_in[1];
    float4* out = (float4*)d_out;
    quantum_layer_kernel<<<GRID, TPB>>>(x, w, out);
}

// round 15
// speedup vs baseline: 8.4000x; 5.2953x over previous
#include <cuda_runtime.h>

#define BATCH 524288u
#define TPB 256
#define GRID 740u            // 148 SMs, single wave
#define STRIDE (GRID * TPB)  // 189440
typedef unsigned long long u64;

// ---- packed f32x2 primitives ----
#define F2MUL(d,a,b)    asm("mul.rn.f32x2 %0, %1, %2;" : "=l"(d) : "l"(a), "l"(b))
#define F2ADD(d,a,b)    asm("add.rn.f32x2 %0, %1, %2;" : "=l"(d) : "l"(a), "l"(b))
#define F2FMA(d,a,b,c)  asm("fma.rn.f32x2 %0, %1, %2, %3;" : "=l"(d) : "l"(a), "l"(b), "l"(c))
#define F2PACK(d,lo,hi) asm("mov.b64 %0, {%1, %2};" : "=l"(d) : "f"(lo), "f"(hi))
#define F2UNPACK(lo,hi,s) asm("mov.b64 {%0, %1}, %2;" : "=f"(lo), "=f"(hi) : "l"(s))
#define F2SWAP(d,s) asm("{\n\t.reg .b32 _l,_h;\n\tmov.b64 {_l,_h}, %1;\n\tmov.b64 %0, {_h,_l};\n\t}" : "=l"(d) : "l"(s))

#define SGNBOTH 0x8000000080000000ULL

// ordered (non-hoistable) 16B shared load
#define LDSC(lo,hi,addr) asm volatile("ld.volatile.shared.v2.b64 {%0, %1}, [%2];" \
    : "=l"(lo), "=l"(hi) : "r"(addr))

__device__ __forceinline__ float2 cmul(float2 a, float2 b) {
    return make_float2(fmaf(a.x, b.x, -a.y * b.y), fmaf(a.x, b.y, a.y * b.x));
}

__device__ __forceinline__ void ry_al(u64& AR, u64& AI, u64& BR, u64& BI,
                                      u64 c2, u64 sA, u64 sB) {
    u64 t1, t2, t3, t4, oAR = AR, oAI = AI;
    F2MUL(t1, c2, AR); F2MUL(t2, c2, AI); F2MUL(t3, c2, BR); F2MUL(t4, c2, BI);
    F2FMA(AR, sA, BR, t1);
    F2FMA(AI, sA, BI, t2);
    F2FMA(BR, sB, oAR, t3);
    F2FMA(BI, sB, oAI, t4);
}

// full circuit for one sample (VERIFIED R10 path) — per-block oracle at the 81
// grid points ONLY. __noinline__ so its register pressure stays out of the
// per-sample fast path.
__device__ __noinline__ float4 qbody(
    float4 xv, const float4* __restrict__ l0c,
    const ulonglong2* __restrict__ dRIp,
    const float4* __restrict__ r0c4, const float4* __restrict__ r1c4,
    const float4* __restrict__ r2c4, const float* __restrict__ w3c)
{
    const u64 NEG1 = 0xBF800000BF800000ULL;
    float xs[4] = {xv.x, xv.y, xv.z, xv.w};

    float2 u0[4], u1[4];
    #pragma unroll
    for (int q = 0; q < 4; q++) {
        float4 cc = l0c[q];
        float sx, cx;
        __sincosf(0.5f * xs[q], &sx, &cx);
        float t  = sx * cc.z;
        float qq = sx * cc.w;
        float m1 = cc.y * t;
        u0[q].x = fmaf(cc.x, cx, -m1);
        u0[q].y = -(cc.y * qq);
        u1[q].x = fmaf(cc.y, cx, cc.x * t);
        u1[q].y = cc.x * qq;
    }
    float2 a01[4], a23[4];
    a01[0] = cmul(u0[0], u0[1]); a01[1] = cmul(u0[0], u1[1]);
    a01[2] = cmul(u1[0], u0[1]); a01[3] = cmul(u1[0], u1[1]);
    a23[0] = cmul(u0[2], u0[3]); a23[1] = cmul(u0[2], u1[3]);
    a23[2] = cmul(u1[2], u0[3]); a23[3] = cmul(u1[2], u1[3]);

    u64 A0R, A0I, A1R, A1I;
    F2PACK(A0R, a01[0].x, a01[3].x); F2PACK(A0I, a01[0].y, a01[3].y);
    F2PACK(A1R, a01[1].x, a01[2].x); F2PACK(A1I, a01[1].y, a01[2].y);
    u64 sR[8], sI[8];
    #pragma unroll
    for (int j = 0; j < 4; j++) {
        u64 BR, BI, nBI, t;
        F2PACK(BR, a23[j].x, a23[j].x);
        F2PACK(BI, a23[j].y, a23[j].y);
        nBI = BI ^ SGNBOTH;
        F2MUL(t, A0R, BR); F2FMA(sR[j],     A0I, nBI, t);
        F2MUL(t, A0R, BI); F2FMA(sI[j],     A0I, BR,  t);
        F2MUL(t, A1R, BR); F2FMA(sR[4 + j], A1I, nBI, t);
        F2MUL(t, A1R, BI); F2FMA(sI[4 + j], A1I, BR,  t);
    }
    #pragma unroll
    for (int p = 0; p < 8; p++) {
        ulonglong2 dv = dRIp[p];
        u64 cR = dv.x, cI = dv.y, ncI = cI ^ SGNBOTH;
        u64 t1, t2, oR = sR[p];
        F2MUL(t1, cR, sR[p]); F2MUL(t2, cR, sI[p]);
        F2FMA(sR[p], ncI, sI[p], t1);
        F2FMA(sI[p], cI,  oR,    t2);
    }
    {
        ulonglong2 rv = *reinterpret_cast<const ulonglong2*>(r0c4);
        u64 c0 = rv.x, svE = rv.y, svO = svE ^ SGNBOTH;
        #pragma unroll
        for (int p = 0; p < 8; p++) {
            u64 sv = (p == 0 || p == 3 || p == 5 || p == 6) ? svE : svO;
            u64 wR, wI, t1, t2;
            F2SWAP(wR, sR[p]); F2SWAP(wI, sI[p]);
            F2MUL(t1, c0, sR[p]); F2MUL(t2, c0, sI[p]);
            F2FMA(sR[p], sv, wR, t1);
            F2FMA(sI[p], sv, wI, t2);
        }
    }
    {
        ulonglong2 rv = *reinterpret_cast<const ulonglong2*>(r1c4);
        u64 c = rv.x, sA = rv.y, sB = sA ^ SGNBOTH;
        ry_al(sR[0], sI[0], sR[6], sI[6], c, sA, sB);
        ry_al(sR[1], sI[1], sR[7], sI[7], c, sA, sB);
        ry_al(sR[2], sI[2], sR[4], sI[4], c, sA, sB);
        ry_al(sR[3], sI[3], sR[5], sI[5], c, sA, sB);
    }
    {
        ulonglong2 rv = *reinterpret_cast<const ulonglong2*>(r2c4);
        u64 c = rv.x, sA = rv.y, sB = sA ^ SGNBOTH;
        ry_al(sR[0], sI[0], sR[3], sI[3], c, sA, sB);
        ry_al(sR[1], sI[1], sR[2], sI[2], c, sA, sB);
        ry_al(sR[7], sI[7], sR[4], sI[4], c, sA, sB);
        ry_al(sR[6], sI[6], sR[5], sI[5], c, sA, sB);
    }
    u64 P[8];
    #pragma unroll
    for (int p = 0; p < 8; p++) {
        u64 t; F2MUL(t, sR[p], sR[p]); F2FMA(P[p], sI[p], sI[p], t);
    }
    u64 CR[4];
    #pragma unroll
    for (int i = 0; i < 4; i++) {
        int p = 2 * i;
        u64 wr, wi, t;
        F2SWAP(wr, sR[p + 1]); F2SWAP(wi, sI[p + 1]);
        F2MUL(t, sR[p], wr); F2FMA(CR[i], sI[p], wi, t);
    }
    u64 sm[4], df[4];
    #pragma unroll
    for (int i = 0; i < 4; i++) {
        F2ADD(sm[i], P[2 * i], P[2 * i + 1]);
        F2FMA(df[i], P[2 * i + 1], NEG1, P[2 * i]);
    }
    u64 t1, t2, Ea, Eb, Ec, Up, Vd, g1, g2;
    F2ADD(t1, df[0], df[1]); F2ADD(t2, df[2], df[3]); F2FMA(Ea, t2, NEG1, t1);
    F2ADD(t1, df[0], df[2]); F2ADD(t2, df[1], df[3]); F2FMA(Eb, t2, NEG1, t1);
    F2ADD(t1, sm[0], sm[2]); F2ADD(t2, sm[1], sm[3]); F2FMA(Ec, t2, NEG1, t1);
    F2FMA(g1, CR[1], NEG1, CR[0]); F2FMA(g2, CR[3], NEG1, CR[2]); F2ADD(Up, g1, g2);
    F2ADD(t1, CR[0], CR[1]); F2ADD(t2, CR[2], CR[3]); F2FMA(Vd, t2, NEG1, t1);

    float eal, eah, ebl, ebh, ecl, ech, upl, uph, vdl, vdh;
    F2UNPACK(eal, eah, Ea); F2UNPACK(ebl, ebh, Eb); F2UNPACK(ecl, ech, Ec);
    F2UNPACK(upl, uph, Up); F2UNPACK(vdl, vdh, Vd);
    float c3 = w3c[0], s3n2 = w3c[1];
    float W13 = eal + eah;
    float W5  = eal - eah;
    float W11 = ebl - ebh;
    float W10 = ecl - ech;
    float C0 = upl + uph;
    float C3 = vdl - vdh;
    float4 o;
    o.x = fmaf(c3, W13, s3n2 * C0);
    o.y = W11;
    o.z = W5;
    o.w = fmaf(c3, W10, s3n2 * C3);
    return o;
}

// one inner cell: acc += v_b * K[cell]  (both output pairs)
#define HCELL(bi, VV) { u64 cx, cy; LDSC(cx, cy, base + (bi) * 16u); \
    F2FMA(ax, VV, cx, ax); F2FMA(ay, VV, cy, ay); }

// one a-block: 9 ordered loads + 16 FMA, then fold into totals with scalar u
#define HBLOCK_FIRST() { unsigned base = kbase; \
    u64 ax, ay; LDSC(ax, ay, base); \
    HCELL(1, v1) HCELL(2, v2) HCELL(3, v3) HCELL(4, v4) \
    HCELL(5, v5) HCELL(6, v6) HCELL(7, v7) HCELL(8, v8) \
    totx = ax; toty = ay; \
    asm volatile("" ::: "memory"); }

#define HBLOCK(A, US) { unsigned base = kbase + (A) * 144u; \
    u64 ax, ay; LDSC(ax, ay, base); \
    HCELL(1, v1) HCELL(2, v2) HCELL(3, v3) HCELL(4, v4) \
    HCELL(5, v5) HCELL(6, v6) HCELL(7, v7) HCELL(8, v8) \
    u64 uu; F2PACK(uu, US, US); \
    F2FMA(totx, uu, ax, totx); F2FMA(toty, uu, ay, toty); \
    asm volatile("" ::: "memory"); }

// per-sample fast path: 9x9 factorized 81-coefficient contraction
__device__ __forceinline__ float4 hbody(float4 xv, unsigned kbase) {
    float Ca, Sa, Cb, Sb, Cc, Sc, Cd, Sd;
    __sincosf(xv.x, &Sa, &Ca);
    __sincosf(xv.y, &Sb, &Cb);
    __sincosf(xv.z, &Sc, &Cc);
    __sincosf(xv.w, &Sd, &Cd);
    // v multipliers (qubits 2,3): [Cd, Sd, Cc, CcCd, CcSd, Sc, ScCd, ScSd]
    float CcCd = Cc * Cd, CcSd = Cc * Sd, ScCd = Sc * Cd, ScSd = Sc * Sd;
    u64 v1, v2, v3, v4, v5, v6, v7, v8;
    F2PACK(v1, Cd, Cd);     F2PACK(v2, Sd, Sd);
    F2PACK(v3, Cc, Cc);     F2PACK(v4, CcCd, CcCd);
    F2PACK(v5, CcSd, CcSd); F2PACK(v6, Sc, Sc);
    F2PACK(v7, ScCd, ScCd); F2PACK(v8, ScSd, ScSd);
    // u multipliers (qubits 0,1) stay scalar: [Cb, Sb, Ca, CaCb, CaSb, Sa, SaCb, SaSb]
    float CaCb = Ca * Cb, CaSb = Ca * Sb, SaCb = Sa * Cb, SaSb = Sa * Sb;

    u64 totx, toty;
    HBLOCK_FIRST()
    HBLOCK(1, Cb)
    HBLOCK(2, Sb)
    HBLOCK(3, Ca)
    HBLOCK(4, CaCb)
    HBLOCK(5, CaSb)
    HBLOCK(6, Sa)
    HBLOCK(7, SaCb)
    HBLOCK(8, SaSb)

    float o0, o1, o2, o3;
    F2UNPACK(o0, o1, totx);
    F2UNPACK(o2, o3, toty);
    return make_float4(o0, o1, o2, o3);
}

__device__ __forceinline__ void xform3(float* kf, int base, int st) {
    float f0 = kf[base], f1 = kf[base + st], f2 = kf[base + 2 * st];
    float a = (f0 + f1 + f2) * 0.3333333333333333f;
    float b = f0 - a;
    float c = (f1 - f2) * 0.5773502691896258f;   // 1/sqrt(3)
    kf[base] = a; kf[base + st] = b; kf[base + 2 * st] = c;
}

__global__ void __launch_bounds__(TPB, 3) quantum_layer_kernel(
    const float4* __restrict__ x, const float* __restrict__ w,
    float4* __restrict__ out)
{
    __shared__ __align__(16) float4 l0c[4];
    __shared__ __align__(16) float4 dRI[8];
    __shared__ __align__(16) float4 r0c4, r1c4, r2c4;
    __shared__ float w3c[2];
    __shared__ __align__(16) float kf[324];   // F-values, then kappa in place

    int tid = threadIdx.x;
    if (tid < 4) {
        float sy, cy, sz, cz;
        __sincosf(0.5f * w[2 * tid + 1], &sy, &cy);
        __sincosf(w[2 * tid], &sz, &cz);
        l0c[tid] = make_float4(cy, sy, cz, sz);
    } else if (tid >= 16 && tid < 32) {
        int k = tid - 16;
        float phi = 0.5f * ( w[8]  * ((__popc(k & 7)  & 1) ? -1.f : 1.f)
                           + w[10] * ((__popc(k & 12) & 1) ? -1.f : 1.f)
                           + w[12] * ((__popc(k & 14) & 1) ? -1.f : 1.f)
                           + w[14] * ((__popc(k & 15) & 1) ? -1.f : 1.f) );
        float sp, cp; __sincosf(phi, &sp, &cp);
        int p = (k < 8) ? k : (k ^ 12);
        int l = (k < 8) ? 0 : 1;
        float* f = reinterpret_cast<float*>(dRI);
        f[4 * p + l]     = cp;
        f[4 * p + 2 + l] = -sp;
    } else if (tid == 32) {
        float s, c; __sincosf(0.5f * w[9], &s, &c);
        r0c4 = make_float4(c, c, -s, s);
    } else if (tid == 33) {
        float s, c; __sincosf(0.5f * w[11], &s, &c);
        r1c4 = make_float4(c, c, -s, -s);
    } else if (tid == 34) {
        float s, c; __sincosf(0.5f * w[13], &s, &c);
        r2c4 = make_float4(c, c, -s, -s);
    } else if (tid == 35) {
        float s, c; __sincosf(w[15], &s, &c);
        w3c[0] = c; w3c[1] = -2.f * s;
    }
    __syncthreads();

    const ulonglong2* dRIp = reinterpret_cast<const ulonglong2*>(dRI);

    // ---- Stage A: evaluate the circuit at the 81 grid points ----
    if (tid < 81) {
        const float TH0 = 0.0f, TH1 = 2.0943951023931953f, TH2 = -2.0943951023931953f;
        int j1 = tid / 27, j2 = (tid / 9) % 3, j3 = (tid / 3) % 3, j4 = tid % 3;
        float th[3] = {TH0, TH1, TH2};
        float4 gx = make_float4(th[j1], th[j2], th[j3], th[j4]);
        float4 r = qbody(gx, l0c, dRIp, &r0c4, &r1c4, &r2c4, w3c);
        kf[tid * 4 + 0] = r.x;
        kf[tid * 4 + 1] = r.y;
        kf[tid * 4 + 2] = r.z;
        kf[tid * 4 + 3] = r.w;
    }
    __syncthreads();

    // ---- Stage B: per-qubit inverse interpolation transforms (in place) ----
    if (tid < 108) { int c = tid >> 2, o = tid & 3; xform3(kf, c * 12 + o, 4); }
    __syncthreads();
    if (tid < 108) { int g = tid / 12, r = tid % 12; xform3(kf, g * 36 + r, 12); }
    __syncthreads();
    if (tid < 108) { int g = tid / 36, r = tid % 36; xform3(kf, g * 108 + r, 36); }
    __syncthreads();
    if (tid < 108) { xform3(kf, tid, 108); }
    __syncthreads();

    unsigned kbase;
    asm("{ .reg .u64 t; cvta.to.shared.u64 t, %1; cvt.u32.u64 %0, t; }"
        : "=r"(kbase) : "l"(kf));

    // ---- Stage C: exactly 2 uniform iterations + balanced per-block tail ----
    unsigned bid = blockIdx.x;
    unsigned b0 = bid * (unsigned)TPB + tid;
    unsigned b1 = b0 + STRIDE;

    unsigned n = (bid < 368u) ? 197u : 196u;
    unsigned tb = 2u * STRIDE + bid * 196u + min(bid, 368u) + (unsigned)tid;
    bool tact = (unsigned)tid < n;

    float4 xv = x[b0];
    {
        float4 cur = xv;
        xv = x[b1];
        out[b0] = hbody(cur, kbase);
    }
    {
        float4 cur = xv;
        if (tact) xv = x[tb];
        out[b1] = hbody(cur, kbase);
    }
    if (tact) {
        out[tb] = hbody(xv, kbase);
    }
}

extern "C" void kernel_launch(void* const* d_in, const int* in_sizes, int n_in,
                              void* d_out, int out_size) {
    const float4* x = (const float4*)d_in[0];
    const float*  w = (const float*)d_in[1];
    float4* out = (float4*)d_out;
    quantum_layer_kernel<<<GRID, TPB>>>(x, w, out);
}

// round 16
// speedup vs baseline: 9.5414x; 1.1359x over previous
#include <cuda_runtime.h>

#define BATCH 524288u
#define TPB 256
#define GRID 740u            // 148 SMs, single wave
#define STRIDE (GRID * TPB)  // 189440
typedef unsigned long long u64;

// ---- packed f32x2 primitives ----
#define F2MUL(d,a,b)    asm("mul.rn.f32x2 %0, %1, %2;" : "=l"(d) : "l"(a), "l"(b))
#define F2ADD(d,a,b)    asm("add.rn.f32x2 %0, %1, %2;" : "=l"(d) : "l"(a), "l"(b))
#define F2FMA(d,a,b,c)  asm("fma.rn.f32x2 %0, %1, %2, %3;" : "=l"(d) : "l"(a), "l"(b), "l"(c))
#define F2PACK(d,lo,hi) asm("mov.b64 %0, {%1, %2};" : "=l"(d) : "f"(lo), "f"(hi))
#define F2UNPACK(lo,hi,s) asm("mov.b64 {%0, %1}, %2;" : "=f"(lo), "=f"(hi) : "l"(s))
#define F2SWAP(d,s) asm("{\n\t.reg .b32 _l,_h;\n\tmov.b64 {_l,_h}, %1;\n\tmov.b64 %0, {_h,_l};\n\t}" : "=l"(d) : "l"(s))

#define SGNBOTH 0x8000000080000000ULL

// ordered (non-hoistable) 16B shared load
#define LDSC(lo,hi,addr) asm volatile("ld.volatile.shared.v2.b64 {%0, %1}, [%2];" \
    : "=l"(lo), "=l"(hi) : "r"(addr))

__device__ __forceinline__ float2 cmul(float2 a, float2 b) {
    return make_float2(fmaf(a.x, b.x, -a.y * b.y), fmaf(a.x, b.y, a.y * b.x));
}

__device__ __forceinline__ void ry_al(u64& AR, u64& AI, u64& BR, u64& BI,
                                      u64 c2, u64 sA, u64 sB) {
    u64 t1, t2, t3, t4, oAR = AR, oAI = AI;
    F2MUL(t1, c2, AR); F2MUL(t2, c2, AI); F2MUL(t3, c2, BR); F2MUL(t4, c2, BI);
    F2FMA(AR, sA, BR, t1);
    F2FMA(AI, sA, BI, t2);
    F2FMA(BR, sB, oAR, t3);
    F2FMA(BI, sB, oAI, t4);
}

// full circuit for one sample (VERIFIED R10 path) — per-block oracle at the 81
// grid points ONLY. __noinline__ keeps its register pressure out of the fast path.
__device__ __noinline__ float4 qbody(
    float4 xv, const float4* __restrict__ l0c,
    const ulonglong2* __restrict__ dRIp,
    const float4* __restrict__ r0c4, const float4* __restrict__ r1c4,
    const float4* __restrict__ r2c4, const float* __restrict__ w3c)
{
    const u64 NEG1 = 0xBF800000BF800000ULL;
    float xs[4] = {xv.x, xv.y, xv.z, xv.w};

    float2 u0[4], u1[4];
    #pragma unroll
    for (int q = 0; q < 4; q++) {
        float4 cc = l0c[q];
        float sx, cx;
        __sincosf(0.5f * xs[q], &sx, &cx);
        float t  = sx * cc.z;
        float qq = sx * cc.w;
        float m1 = cc.y * t;
        u0[q].x = fmaf(cc.x, cx, -m1);
        u0[q].y = -(cc.y * qq);
        u1[q].x = fmaf(cc.y, cx, cc.x * t);
        u1[q].y = cc.x * qq;
    }
    float2 a01[4], a23[4];
    a01[0] = cmul(u0[0], u0[1]); a01[1] = cmul(u0[0], u1[1]);
    a01[2] = cmul(u1[0], u0[1]); a01[3] = cmul(u1[0], u1[1]);
    a23[0] = cmul(u0[2], u0[3]); a23[1] = cmul(u0[2], u1[3]);
    a23[2] = cmul(u1[2], u0[3]); a23[3] = cmul(u1[2], u1[3]);

    u64 A0R, A0I, A1R, A1I;
    F2PACK(A0R, a01[0].x, a01[3].x); F2PACK(A0I, a01[0].y, a01[3].y);
    F2PACK(A1R, a01[1].x, a01[2].x); F2PACK(A1I, a01[1].y, a01[2].y);
    u64 sR[8], sI[8];
    #pragma unroll
    for (int j = 0; j < 4; j++) {
        u64 BR, BI, nBI, t;
        F2PACK(BR, a23[j].x, a23[j].x);
        F2PACK(BI, a23[j].y, a23[j].y);
        nBI = BI ^ SGNBOTH;
        F2MUL(t, A0R, BR); F2FMA(sR[j],     A0I, nBI, t);
        F2MUL(t, A0R, BI); F2FMA(sI[j],     A0I, BR,  t);
        F2MUL(t, A1R, BR); F2FMA(sR[4 + j], A1I, nBI, t);
        F2MUL(t, A1R, BI); F2FMA(sI[4 + j], A1I, BR,  t);
    }
    #pragma unroll
    for (int p = 0; p < 8; p++) {
        ulonglong2 dv = dRIp[p];
        u64 cR = dv.x, cI = dv.y, ncI = cI ^ SGNBOTH;
        u64 t1, t2, oR = sR[p];
        F2MUL(t1, cR, sR[p]); F2MUL(t2, cR, sI[p]);
        F2FMA(sR[p], ncI, sI[p], t1);
        F2FMA(sI[p], cI,  oR,    t2);
    }
    {
        ulonglong2 rv = *reinterpret_cast<const ulonglong2*>(r0c4);
        u64 c0 = rv.x, svE = rv.y, svO = svE ^ SGNBOTH;
        #pragma unroll
        for (int p = 0; p < 8; p++) {
            u64 sv = (p == 0 || p == 3 || p == 5 || p == 6) ? svE : svO;
            u64 wR, wI, t1, t2;
            F2SWAP(wR, sR[p]); F2SWAP(wI, sI[p]);
            F2MUL(t1, c0, sR[p]); F2MUL(t2, c0, sI[p]);
            F2FMA(sR[p], sv, wR, t1);
            F2FMA(sI[p], sv, wI, t2);
        }
    }
    {
        ulonglong2 rv = *reinterpret_cast<const ulonglong2*>(r1c4);
        u64 c = rv.x, sA = rv.y, sB = sA ^ SGNBOTH;
        ry_al(sR[0], sI[0], sR[6], sI[6], c, sA, sB);
        ry_al(sR[1], sI[1], sR[7], sI[7], c, sA, sB);
        ry_al(sR[2], sI[2], sR[4], sI[4], c, sA, sB);
        ry_al(sR[3], sI[3], sR[5], sI[5], c, sA, sB);
    }
    {
        ulonglong2 rv = *reinterpret_cast<const ulonglong2*>(r2c4);
        u64 c = rv.x, sA = rv.y, sB = sA ^ SGNBOTH;
        ry_al(sR[0], sI[0], sR[3], sI[3], c, sA, sB);
        ry_al(sR[1], sI[1], sR[2], sI[2], c, sA, sB);
        ry_al(sR[7], sI[7], sR[4], sI[4], c, sA, sB);
        ry_al(sR[6], sI[6], sR[5], sI[5], c, sA, sB);
    }
    u64 P[8];
    #pragma unroll
    for (int p = 0; p < 8; p++) {
        u64 t; F2MUL(t, sR[p], sR[p]); F2FMA(P[p], sI[p], sI[p], t);
    }
    u64 CR[4];
    #pragma unroll
    for (int i = 0; i < 4; i++) {
        int p = 2 * i;
        u64 wr, wi, t;
        F2SWAP(wr, sR[p + 1]); F2SWAP(wi, sI[p + 1]);
        F2MUL(t, sR[p], wr); F2FMA(CR[i], sI[p], wi, t);
    }
    u64 sm[4], df[4];
    #pragma unroll
    for (int i = 0; i < 4; i++) {
        F2ADD(sm[i], P[2 * i], P[2 * i + 1]);
        F2FMA(df[i], P[2 * i + 1], NEG1, P[2 * i]);
    }
    u64 t1, t2, Ea, Eb, Ec, Up, Vd, g1, g2;
    F2ADD(t1, df[0], df[1]); F2ADD(t2, df[2], df[3]); F2FMA(Ea, t2, NEG1, t1);
    F2ADD(t1, df[0], df[2]); F2ADD(t2, df[1], df[3]); F2FMA(Eb, t2, NEG1, t1);
    F2ADD(t1, sm[0], sm[2]); F2ADD(t2, sm[1], sm[3]); F2FMA(Ec, t2, NEG1, t1);
    F2FMA(g1, CR[1], NEG1, CR[0]); F2FMA(g2, CR[3], NEG1, CR[2]); F2ADD(Up, g1, g2);
    F2ADD(t1, CR[0], CR[1]); F2ADD(t2, CR[2], CR[3]); F2FMA(Vd, t2, NEG1, t1);

    float eal, eah, ebl, ebh, ecl, ech, upl, uph, vdl, vdh;
    F2UNPACK(eal, eah, Ea); F2UNPACK(ebl, ebh, Eb); F2UNPACK(ecl, ech, Ec);
    F2UNPACK(upl, uph, Up); F2UNPACK(vdl, vdh, Vd);
    float c3 = w3c[0], s3n2 = w3c[1];
    float W13 = eal + eah;
    float W5  = eal - eah;
    float W11 = ebl - ebh;
    float W10 = ecl - ech;
    float C0 = upl + uph;
    float C3 = vdl - vdh;
    float4 o;
    o.x = fmaf(c3, W13, s3n2 * C0);
    o.y = W11;
    o.z = W5;
    o.w = fmaf(c3, W10, s3n2 * C3);
    return o;
}

// ---------- single-sample contraction (tail) ----------
#define HCELL(bi, VV) { u64 cx, cy; LDSC(cx, cy, base + (bi) * 16u); \
    F2FMA(ax, VV, cx, ax); F2FMA(ay, VV, cy, ay); }

#define HBLOCK_FIRST() { unsigned base = kbase; \
    u64 ax, ay; LDSC(ax, ay, base); \
    HCELL(1, v1) HCELL(2, v2) HCELL(3, v3) HCELL(4, v4) \
    HCELL(5, v5) HCELL(6, v6) HCELL(7, v7) HCELL(8, v8) \
    totx = ax; toty = ay; \
    asm volatile("" ::: "memory"); }

#define HBLOCK(A, US) { unsigned base = kbase + (A) * 144u; \
    u64 ax, ay; LDSC(ax, ay, base); \
    HCELL(1, v1) HCELL(2, v2) HCELL(3, v3) HCELL(4, v4) \
    HCELL(5, v5) HCELL(6, v6) HCELL(7, v7) HCELL(8, v8) \
    u64 uu; F2PACK(uu, US, US); \
    F2FMA(totx, uu, ax, totx); F2FMA(toty, uu, ay, toty); \
    asm volatile("" ::: "memory"); }

__device__ __forceinline__ float4 hbody(float4 xv, unsigned kbase) {
    float Ca, Sa, Cb, Sb, Cc, Sc, Cd, Sd;
    __sincosf(xv.x, &Sa, &Ca);
    __sincosf(xv.y, &Sb, &Cb);
    __sincosf(xv.z, &Sc, &Cc);
    __sincosf(xv.w, &Sd, &Cd);
    float CcCd = Cc * Cd, CcSd = Cc * Sd, ScCd = Sc * Cd, ScSd = Sc * Sd;
    u64 v1, v2, v3, v4, v5, v6, v7, v8;
    F2PACK(v1, Cd, Cd);     F2PACK(v2, Sd, Sd);
    F2PACK(v3, Cc, Cc);     F2PACK(v4, CcCd, CcCd);
    F2PACK(v5, CcSd, CcSd); F2PACK(v6, Sc, Sc);
    F2PACK(v7, ScCd, ScCd); F2PACK(v8, ScSd, ScSd);
    float CaCb = Ca * Cb, CaSb = Ca * Sb, SaCb = Sa * Cb, SaSb = Sa * Sb;

    u64 totx, toty;
    HBLOCK_FIRST()
    HBLOCK(1, Cb)
    HBLOCK(2, Sb)
    HBLOCK(3, Ca)
    HBLOCK(4, CaCb)
    HBLOCK(5, CaSb)
    HBLOCK(6, Sa)
    HBLOCK(7, SaCb)
    HBLOCK(8, SaSb)

    float o0, o1, o2, o3;
    F2UNPACK(o0, o1, totx);
    F2UNPACK(o2, o3, toty);
    return make_float4(o0, o1, o2, o3);
}

// ---------- dual-sample contraction: 1 coefficient load feeds 4 FMAs ----------
#define H2CELL(bi, VA, VB) { u64 cx, cy; LDSC(cx, cy, base + (bi) * 16u); \
    F2FMA(axa, VA, cx, axa); F2FMA(aya, VA, cy, aya); \
    F2FMA(axb, VB, cx, axb); F2FMA(ayb, VB, cy, ayb); }

#define H2BLOCK_BODY() \
    u64 axa, aya, axb, ayb; \
    { u64 cx, cy; LDSC(cx, cy, base); axa = cx; aya = cy; axb = cx; ayb = cy; } \
    H2CELL(1, va1, vb1) H2CELL(2, va2, vb2) H2CELL(3, va3, vb3) H2CELL(4, va4, vb4) \
    H2CELL(5, va5, vb5) H2CELL(6, va6, vb6) H2CELL(7, va7, vb7) H2CELL(8, va8, vb8)

#define H2BLOCK_FIRST() { unsigned base = kbase; \
    H2BLOCK_BODY() \
    totxa = axa; totya = aya; totxb = axb; totyb = ayb; \
    asm volatile("" ::: "memory"); }

#define H2BLOCK(A, USA, USB) { unsigned base = kbase + (A) * 144u; \
    H2BLOCK_BODY() \
    u64 uua, uub; F2PACK(uua, USA, USA); F2PACK(uub, USB, USB); \
    F2FMA(totxa, uua, axa, totxa); F2FMA(totya, uua, aya, totya); \
    F2FMA(totxb, uub, axb, totxb); F2FMA(totyb, uub, ayb, totyb); \
    asm volatile("" ::: "memory"); }

__device__ __forceinline__ void hbody2(float4 xa, float4 xb, unsigned kbase,
                                       float4& oa, float4& ob) {
    float Ca, Sa, Cb, Sb, Cc, Sc, Cd, Sd;
    __sincosf(xa.x, &Sa, &Ca);
    __sincosf(xa.y, &Sb, &Cb);
    __sincosf(xa.z, &Sc, &Cc);
    __sincosf(xa.w, &Sd, &Cd);
    float Ea, Ta, Eb2, Tb, Ec2, Tc, Ed, Td;
    __sincosf(xb.x, &Ta, &Ea);
    __sincosf(xb.y, &Tb, &Eb2);
    __sincosf(xb.z, &Tc, &Ec2);
    __sincosf(xb.w, &Td, &Ed);

    // v packs (qubits 2,3) per sample
    u64 va1, va2, va3, va4, va5, va6, va7, va8;
    {
        float p4 = Cc * Cd, p5 = Cc * Sd, p7 = Sc * Cd, p8 = Sc * Sd;
        F2PACK(va1, Cd, Cd); F2PACK(va2, Sd, Sd); F2PACK(va3, Cc, Cc);
        F2PACK(va4, p4, p4); F2PACK(va5, p5, p5); F2PACK(va6, Sc, Sc);
        F2PACK(va7, p7, p7); F2PACK(va8, p8, p8);
    }
    u64 vb1, vb2, vb3, vb4, vb5, vb6, vb7, vb8;
    {
        float p4 = Ec2 * Ed, p5 = Ec2 * Td, p7 = Tc * Ed, p8 = Tc * Td;
        F2PACK(vb1, Ed, Ed); F2PACK(vb2, Td, Td); F2PACK(vb3, Ec2, Ec2);
        F2PACK(vb4, p4, p4); F2PACK(vb5, p5, p5); F2PACK(vb6, Tc, Tc);
        F2PACK(vb7, p7, p7); F2PACK(vb8, p8, p8);
    }
    // u scalars (qubits 0,1) per sample
    float uCaCb = Ca * Cb, uCaSb = Ca * Sb, uSaCb = Sa * Cb, uSaSb = Sa * Sb;
    float wCaCb = Ea * Eb2, wCaSb = Ea * Tb, wSaCb = Ta * Eb2, wSaSb = Ta * Tb;

    u64 totxa, totya, totxb, totyb;
    H2BLOCK_FIRST()
    H2BLOCK(1, Cb, Eb2)
    H2BLOCK(2, Sb, Tb)
    H2BLOCK(3, Ca, Ea)
    H2BLOCK(4, uCaCb, wCaCb)
    H2BLOCK(5, uCaSb, wCaSb)
    H2BLOCK(6, Sa, Ta)
    H2BLOCK(7, uSaCb, wSaCb)
    H2BLOCK(8, uSaSb, wSaSb)

    float o0, o1, o2, o3;
    F2UNPACK(o0, o1, totxa); F2UNPACK(o2, o3, totya);
    oa = make_float4(o0, o1, o2, o3);
    F2UNPACK(o0, o1, totxb); F2UNPACK(o2, o3, totyb);
    ob = make_float4(o0, o1, o2, o3);
}

__device__ __forceinline__ void xform3(float* kf, int base, int st) {
    float f0 = kf[base], f1 = kf[base + st], f2 = kf[base + 2 * st];
    float a = (f0 + f1 + f2) * 0.3333333333333333f;
    float b = f0 - a;
    float c = (f1 - f2) * 0.5773502691896258f;   // 1/sqrt(3)
    kf[base] = a; kf[base + st] = b; kf[base + 2 * st] = c;
}

__global__ void __launch_bounds__(TPB, 3) quantum_layer_kernel(
    const float4* __restrict__ x, const float* __restrict__ w,
    float4* __restrict__ out)
{
    __shared__ __align__(16) float4 l0c[4];
    __shared__ __align__(16) float4 dRI[8];
    __shared__ __align__(16) float4 r0c4, r1c4, r2c4;
    __shared__ float w3c[2];
    __shared__ __align__(16) float kf[324];   // F-values, then kappa in place

    int tid = threadIdx.x;
    if (tid < 4) {
        float sy, cy, sz, cz;
        __sincosf(0.5f * w[2 * tid + 1], &sy, &cy);
        __sincosf(w[2 * tid], &sz, &cz);
        l0c[tid] = make_float4(cy, sy, cz, sz);
    } else if (tid >= 16 && tid < 32) {
        int k = tid - 16;
        float phi = 0.5f * ( w[8]  * ((__popc(k & 7)  & 1) ? -1.f : 1.f)
                           + w[10] * ((__popc(k & 12) & 1) ? -1.f : 1.f)
                           + w[12] * ((__popc(k & 14) & 1) ? -1.f : 1.f)
                           + w[14] * ((__popc(k & 15) & 1) ? -1.f : 1.f) );
        float sp, cp; __sincosf(phi, &sp, &cp);
        int p = (k < 8) ? k : (k ^ 12);
        int l = (k < 8) ? 0 : 1;
        float* f = reinterpret_cast<float*>(dRI);
        f[4 * p + l]     = cp;
        f[4 * p + 2 + l] = -sp;
    } else if (tid == 32) {
        float s, c; __sincosf(0.5f * w[9], &s, &c);
        r0c4 = make_float4(c, c, -s, s);
    } else if (tid == 33) {
        float s, c; __sincosf(0.5f * w[11], &s, &c);
        r1c4 = make_float4(c, c, -s, -s);
    } else if (tid == 34) {
        float s, c; __sincosf(0.5f * w[13], &s, &c);
        r2c4 = make_float4(c, c, -s, -s);
    } else if (tid == 35) {
        float s, c; __sincosf(w[15], &s, &c);
        w3c[0] = c; w3c[1] = -2.f * s;
    }
    __syncthreads();

    const ulonglong2* dRIp = reinterpret_cast<const ulonglong2*>(dRI);

    // ---- Stage A: evaluate the circuit at the 81 grid points ----
    if (tid < 81) {
        const float TH0 = 0.0f, TH1 = 2.0943951023931953f, TH2 = -2.0943951023931953f;
        int j1 = tid / 27, j2 = (tid / 9) % 3, j3 = (tid / 3) % 3, j4 = tid % 3;
        float th[3] = {TH0, TH1, TH2};
        float4 gx = make_float4(th[j1], th[j2], th[j3], th[j4]);
        float4 r = qbody(gx, l0c, dRIp, &r0c4, &r1c4, &r2c4, w3c);
        kf[tid * 4 + 0] = r.x;
        kf[tid * 4 + 1] = r.y;
        kf[tid * 4 + 2] = r.z;
        kf[tid * 4 + 3] = r.w;
    }
    __syncthreads();

    // ---- Stage B: per-qubit inverse interpolation transforms (in place) ----
    if (tid < 108) { int c = tid >> 2, o = tid & 3; xform3(kf, c * 12 + o, 4); }
    __syncthreads();
    if (tid < 108) { int g = tid / 12, r = tid % 12; xform3(kf, g * 36 + r, 12); }
    __syncthreads();
    if (tid < 108) { int g = tid / 36, r = tid % 36; xform3(kf, g * 108 + r, 36); }
    __syncthreads();
    if (tid < 108) { xform3(kf, tid, 108); }
    __syncthreads();

    unsigned kbase;
    asm("{ .reg .u64 t; cvta.to.shared.u64 t, %1; cvt.u32.u64 %0, t; }"
        : "=r"(kbase) : "l"(kf));

    // ---- Stage C: dual-sample main pass + balanced per-block tail ----
    unsigned bid = blockIdx.x;
    unsigned b0 = bid * (unsigned)TPB + tid;
    unsigned b1 = b0 + STRIDE;

    unsigned n = (bid < 368u) ? 197u : 196u;
    unsigned tb = 2u * STRIDE + bid * 196u + min(bid, 368u) + (unsigned)tid;
    bool tact = (unsigned)tid < n;

    float4 xa = x[b0];
    float4 xb = x[b1];
    float4 xt = tact ? x[tb] : xa;   // prefetch tail before the heavy pass

    float4 oa, ob;
    hbody2(xa, xb, kbase, oa, ob);
    out[b0] = oa;
    out[b1] = ob;

    if (tact) {
        out[tb] = hbody(xt, kbase);
    }
}

extern "C" void kernel_launch(void* const* d_in, const int* in_sizes, int n_in,
                              void* d_out, int out_size) {
    const float4* x = (const float4*)d_in[0];
    const float*  w = (const float*)d_in[1];
    float4* out = (float4*)d_out;
    quantum_layer_kernel<<<GRID, TPB>>>(x, w, out);
}

// round 17
// speedup vs baseline: 9.6645x; 1.0129x over previous
#include <cuda_runtime.h>

#define BATCH 524288u
#define TPB 256
#define GRID 740u            // 148 SMs, single wave
#define STRIDE (GRID * TPB)  // 189440
typedef unsigned long long u64;

// ---- packed f32x2 primitives ----
#define F2MUL(d,a,b)    asm("mul.rn.f32x2 %0, %1, %2;" : "=l"(d) : "l"(a), "l"(b))
#define F2ADD(d,a,b)    asm("add.rn.f32x2 %0, %1, %2;" : "=l"(d) : "l"(a), "l"(b))
#define F2FMA(d,a,b,c)  asm("fma.rn.f32x2 %0, %1, %2, %3;" : "=l"(d) : "l"(a), "l"(b), "l"(c))
#define F2PACK(d,lo,hi) asm("mov.b64 %0, {%1, %2};" : "=l"(d) : "f"(lo), "f"(hi))
#define F2UNPACK(lo,hi,s) asm("mov.b64 {%0, %1}, %2;" : "=f"(lo), "=f"(hi) : "l"(s))
#define F2SWAP(d,s) asm("{\n\t.reg .b32 _l,_h;\n\tmov.b64 {_l,_h}, %1;\n\tmov.b64 %0, {_h,_l};\n\t}" : "=l"(d) : "l"(s))

#define SGNBOTH 0x8000000080000000ULL

// ordered (non-hoistable) 16B shared load
#define LDSC(lo,hi,addr) asm volatile("ld.volatile.shared.v2.b64 {%0, %1}, [%2];" \
    : "=l"(lo), "=l"(hi) : "r"(addr))

__device__ __forceinline__ float2 cmul(float2 a, float2 b) {
    return make_float2(fmaf(a.x, b.x, -a.y * b.y), fmaf(a.x, b.y, a.y * b.x));
}

__device__ __forceinline__ void ry_al(u64& AR, u64& AI, u64& BR, u64& BI,
                                      u64 c2, u64 sA, u64 sB) {
    u64 t1, t2, t3, t4, oAR = AR, oAI = AI;
    F2MUL(t1, c2, AR); F2MUL(t2, c2, AI); F2MUL(t3, c2, BR); F2MUL(t4, c2, BI);
    F2FMA(AR, sA, BR, t1);
    F2FMA(AI, sA, BI, t2);
    F2FMA(BR, sB, oAR, t3);
    F2FMA(BI, sB, oAI, t4);
}

// full circuit for one sample (VERIFIED R10 path) — per-block oracle at the 81
// grid points ONLY. __noinline__ keeps its register pressure out of the fast path.
__device__ __noinline__ float4 qbody(
    float4 xv, const float4* __restrict__ l0c,
    const ulonglong2* __restrict__ dRIp,
    const float4* __restrict__ r0c4, const float4* __restrict__ r1c4,
    const float4* __restrict__ r2c4, const float* __restrict__ w3c)
{
    const u64 NEG1 = 0xBF800000BF800000ULL;
    float xs[4] = {xv.x, xv.y, xv.z, xv.w};

    float2 u0[4], u1[4];
    #pragma unroll
    for (int q = 0; q < 4; q++) {
        float4 cc = l0c[q];
        float sx, cx;
        __sincosf(0.5f * xs[q], &sx, &cx);
        float t  = sx * cc.z;
        float qq = sx * cc.w;
        float m1 = cc.y * t;
        u0[q].x = fmaf(cc.x, cx, -m1);
        u0[q].y = -(cc.y * qq);
        u1[q].x = fmaf(cc.y, cx, cc.x * t);
        u1[q].y = cc.x * qq;
    }
    float2 a01[4], a23[4];
    a01[0] = cmul(u0[0], u0[1]); a01[1] = cmul(u0[0], u1[1]);
    a01[2] = cmul(u1[0], u0[1]); a01[3] = cmul(u1[0], u1[1]);
    a23[0] = cmul(u0[2], u0[3]); a23[1] = cmul(u0[2], u1[3]);
    a23[2] = cmul(u1[2], u0[3]); a23[3] = cmul(u1[2], u1[3]);

    u64 A0R, A0I, A1R, A1I;
    F2PACK(A0R, a01[0].x, a01[3].x); F2PACK(A0I, a01[0].y, a01[3].y);
    F2PACK(A1R, a01[1].x, a01[2].x); F2PACK(A1I, a01[1].y, a01[2].y);
    u64 sR[8], sI[8];
    #pragma unroll
    for (int j = 0; j < 4; j++) {
        u64 BR, BI, nBI, t;
        F2PACK(BR, a23[j].x, a23[j].x);
        F2PACK(BI, a23[j].y, a23[j].y);
        nBI = BI ^ SGNBOTH;
        F2MUL(t, A0R, BR); F2FMA(sR[j],     A0I, nBI, t);
        F2MUL(t, A0R, BI); F2FMA(sI[j],     A0I, BR,  t);
        F2MUL(t, A1R, BR); F2FMA(sR[4 + j], A1I, nBI, t);
        F2MUL(t, A1R, BI); F2FMA(sI[4 + j], A1I, BR,  t);
    }
    #pragma unroll
    for (int p = 0; p < 8; p++) {
        ulonglong2 dv = dRIp[p];
        u64 cR = dv.x, cI = dv.y, ncI = cI ^ SGNBOTH;
        u64 t1, t2, oR = sR[p];
        F2MUL(t1, cR, sR[p]); F2MUL(t2, cR, sI[p]);
        F2FMA(sR[p], ncI, sI[p], t1);
        F2FMA(sI[p], cI,  oR,    t2);
    }
    {
        ulonglong2 rv = *reinterpret_cast<const ulonglong2*>(r0c4);
        u64 c0 = rv.x, svE = rv.y, svO = svE ^ SGNBOTH;
        #pragma unroll
        for (int p = 0; p < 8; p++) {
            u64 sv = (p == 0 || p == 3 || p == 5 || p == 6) ? svE : svO;
            u64 wR, wI, t1, t2;
            F2SWAP(wR, sR[p]); F2SWAP(wI, sI[p]);
            F2MUL(t1, c0, sR[p]); F2MUL(t2, c0, sI[p]);
            F2FMA(sR[p], sv, wR, t1);
            F2FMA(sI[p], sv, wI, t2);
        }
    }
    {
        ulonglong2 rv = *reinterpret_cast<const ulonglong2*>(r1c4);
        u64 c = rv.x, sA = rv.y, sB = sA ^ SGNBOTH;
        ry_al(sR[0], sI[0], sR[6], sI[6], c, sA, sB);
        ry_al(sR[1], sI[1], sR[7], sI[7], c, sA, sB);
        ry_al(sR[2], sI[2], sR[4], sI[4], c, sA, sB);
        ry_al(sR[3], sI[3], sR[5], sI[5], c, sA, sB);
    }
    {
        ulonglong2 rv = *reinterpret_cast<const ulonglong2*>(r2c4);
        u64 c = rv.x, sA = rv.y, sB = sA ^ SGNBOTH;
        ry_al(sR[0], sI[0], sR[3], sI[3], c, sA, sB);
        ry_al(sR[1], sI[1], sR[2], sI[2], c, sA, sB);
        ry_al(sR[7], sI[7], sR[4], sI[4], c, sA, sB);
        ry_al(sR[6], sI[6], sR[5], sI[5], c, sA, sB);
    }
    u64 P[8];
    #pragma unroll
    for (int p = 0; p < 8; p++) {
        u64 t; F2MUL(t, sR[p], sR[p]); F2FMA(P[p], sI[p], sI[p], t);
    }
    u64 CR[4];
    #pragma unroll
    for (int i = 0; i < 4; i++) {
        int p = 2 * i;
        u64 wr, wi, t;
        F2SWAP(wr, sR[p + 1]); F2SWAP(wi, sI[p + 1]);
        F2MUL(t, sR[p], wr); F2FMA(CR[i], sI[p], wi, t);
    }
    u64 sm[4], df[4];
    #pragma unroll
    for (int i = 0; i < 4; i++) {
        F2ADD(sm[i], P[2 * i], P[2 * i + 1]);
        F2FMA(df[i], P[2 * i + 1], NEG1, P[2 * i]);
    }
    u64 t1, t2, Ea, Eb, Ec, Up, Vd, g1, g2;
    F2ADD(t1, df[0], df[1]); F2ADD(t2, df[2], df[3]); F2FMA(Ea, t2, NEG1, t1);
    F2ADD(t1, df[0], df[2]); F2ADD(t2, df[1], df[3]); F2FMA(Eb, t2, NEG1, t1);
    F2ADD(t1, sm[0], sm[2]); F2ADD(t2, sm[1], sm[3]); F2FMA(Ec, t2, NEG1, t1);
    F2FMA(g1, CR[1], NEG1, CR[0]); F2FMA(g2, CR[3], NEG1, CR[2]); F2ADD(Up, g1, g2);
    F2ADD(t1, CR[0], CR[1]); F2ADD(t2, CR[2], CR[3]); F2FMA(Vd, t2, NEG1, t1);

    float eal, eah, ebl, ebh, ecl, ech, upl, uph, vdl, vdh;
    F2UNPACK(eal, eah, Ea); F2UNPACK(ebl, ebh, Eb); F2UNPACK(ecl, ech, Ec);
    F2UNPACK(upl, uph, Up); F2UNPACK(vdl, vdh, Vd);
    float c3 = w3c[0], s3n2 = w3c[1];
    float W13 = eal + eah;
    float W5  = eal - eah;
    float W11 = ebl - ebh;
    float W10 = ecl - ech;
    float C0 = upl + uph;
    float C3 = vdl - vdh;
    float4 o;
    o.x = fmaf(c3, W13, s3n2 * C0);
    o.y = W11;
    o.z = W5;
    o.w = fmaf(c3, W10, s3n2 * C3);
    return o;
}

// ---------- dual-sample contraction: 1 coefficient load feeds 4 FMAs ----------
#define H2CELL(bi, VA, VB) { u64 cx, cy; LDSC(cx, cy, base + (bi) * 16u); \
    F2FMA(axa, VA, cx, axa); F2FMA(aya, VA, cy, aya); \
    F2FMA(axb, VB, cx, axb); F2FMA(ayb, VB, cy, ayb); }

#define H2BLOCK_BODY() \
    u64 axa, aya, axb, ayb; \
    { u64 cx, cy; LDSC(cx, cy, base); axa = cx; aya = cy; axb = cx; ayb = cy; } \
    H2CELL(1, va1, vb1) H2CELL(2, va2, vb2) H2CELL(3, va3, vb3) H2CELL(4, va4, vb4) \
    H2CELL(5, va5, vb5) H2CELL(6, va6, vb6) H2CELL(7, va7, vb7) H2CELL(8, va8, vb8)

#define H2BLOCK_FIRST() { unsigned base = kbase; \
    H2BLOCK_BODY() \
    totxa = axa; totya = aya; totxb = axb; totyb = ayb; \
    asm volatile("" ::: "memory"); }

#define H2BLOCK(A, USA, USB) { unsigned base = kbase + (A) * 144u; \
    H2BLOCK_BODY() \
    u64 uua, uub; F2PACK(uua, USA, USA); F2PACK(uub, USB, USB); \
    F2FMA(totxa, uua, axa, totxa); F2FMA(totya, uua, aya, totya); \
    F2FMA(totxb, uub, axb, totxb); F2FMA(totyb, uub, ayb, totyb); \
    asm volatile("" ::: "memory"); }

__device__ __forceinline__ void hbody2(float4 xa, float4 xb, unsigned kbase,
                                       float4& oa, float4& ob) {
    float Ca, Sa, Cb, Sb, Cc, Sc, Cd, Sd;
    __sincosf(xa.x, &Sa, &Ca);
    __sincosf(xa.y, &Sb, &Cb);
    __sincosf(xa.z, &Sc, &Cc);
    __sincosf(xa.w, &Sd, &Cd);
    float Ea, Ta, Eb2, Tb, Ec2, Tc, Ed, Td;
    __sincosf(xb.x, &Ta, &Ea);
    __sincosf(xb.y, &Tb, &Eb2);
    __sincosf(xb.z, &Tc, &Ec2);
    __sincosf(xb.w, &Td, &Ed);

    // v packs (qubits 2,3) per sample
    u64 va1, va2, va3, va4, va5, va6, va7, va8;
    {
        float p4 = Cc * Cd, p5 = Cc * Sd, p7 = Sc * Cd, p8 = Sc * Sd;
        F2PACK(va1, Cd, Cd); F2PACK(va2, Sd, Sd); F2PACK(va3, Cc, Cc);
        F2PACK(va4, p4, p4); F2PACK(va5, p5, p5); F2PACK(va6, Sc, Sc);
        F2PACK(va7, p7, p7); F2PACK(va8, p8, p8);
    }
    u64 vb1, vb2, vb3, vb4, vb5, vb6, vb7, vb8;
    {
        float p4 = Ec2 * Ed, p5 = Ec2 * Td, p7 = Tc * Ed, p8 = Tc * Td;
        F2PACK(vb1, Ed, Ed); F2PACK(vb2, Td, Td); F2PACK(vb3, Ec2, Ec2);
        F2PACK(vb4, p4, p4); F2PACK(vb5, p5, p5); F2PACK(vb6, Tc, Tc);
        F2PACK(vb7, p7, p7); F2PACK(vb8, p8, p8);
    }
    // u scalars (qubits 0,1) per sample
    float uCaCb = Ca * Cb, uCaSb = Ca * Sb, uSaCb = Sa * Cb, uSaSb = Sa * Sb;
    float wCaCb = Ea * Eb2, wCaSb = Ea * Tb, wSaCb = Ta * Eb2, wSaSb = Ta * Tb;

    u64 totxa, totya, totxb, totyb;
    H2BLOCK_FIRST()
    H2BLOCK(1, Cb, Eb2)
    H2BLOCK(2, Sb, Tb)
    H2BLOCK(3, Ca, Ea)
    H2BLOCK(4, uCaCb, wCaCb)
    H2BLOCK(5, uCaSb, wCaSb)
    H2BLOCK(6, Sa, Ta)
    H2BLOCK(7, uSaCb, wSaCb)
    H2BLOCK(8, uSaSb, wSaSb)

    float o0, o1, o2, o3;
    F2UNPACK(o0, o1, totxa); F2UNPACK(o2, o3, totya);
    oa = make_float4(o0, o1, o2, o3);
    F2UNPACK(o0, o1, totxb); F2UNPACK(o2, o3, totyb);
    ob = make_float4(o0, o1, o2, o3);
}

__device__ __forceinline__ void xform3(float* kf, int base, int st) {
    float f0 = kf[base], f1 = kf[base + st], f2 = kf[base + 2 * st];
    float a = (f0 + f1 + f2) * 0.3333333333333333f;
    float b = f0 - a;
    float c = (f1 - f2) * 0.5773502691896258f;   // 1/sqrt(3)
    kf[base] = a; kf[base + st] = b; kf[base + 2 * st] = c;
}

__global__ void __launch_bounds__(TPB, 3) quantum_layer_kernel(
    const float4* __restrict__ x, const float* __restrict__ w,
    float4* __restrict__ out)
{
    __shared__ __align__(16) float4 l0c[4];
    __shared__ __align__(16) float4 dRI[8];
    __shared__ __align__(16) float4 r0c4, r1c4, r2c4;
    __shared__ float w3c[2];
    __shared__ __align__(16) float kf[324];   // F-values, then kappa in place

    int tid = threadIdx.x;
    if (tid < 4) {
        float sy, cy, sz, cz;
        __sincosf(0.5f * w[2 * tid + 1], &sy, &cy);
        __sincosf(w[2 * tid], &sz, &cz);
        l0c[tid] = make_float4(cy, sy, cz, sz);
    } else if (tid >= 16 && tid < 32) {
        int k = tid - 16;
        float phi = 0.5f * ( w[8]  * ((__popc(k & 7)  & 1) ? -1.f : 1.f)
                           + w[10] * ((__popc(k & 12) & 1) ? -1.f : 1.f)
                           + w[12] * ((__popc(k & 14) & 1) ? -1.f : 1.f)
                           + w[14] * ((__popc(k & 15) & 1) ? -1.f : 1.f) );
        float sp, cp; __sincosf(phi, &sp, &cp);
        int p = (k < 8) ? k : (k ^ 12);
        int l = (k < 8) ? 0 : 1;
        float* f = reinterpret_cast<float*>(dRI);
        f[4 * p + l]     = cp;
        f[4 * p + 2 + l] = -sp;
    } else if (tid == 32) {
        float s, c; __sincosf(0.5f * w[9], &s, &c);
        r0c4 = make_float4(c, c, -s, s);
    } else if (tid == 33) {
        float s, c; __sincosf(0.5f * w[11], &s, &c);
        r1c4 = make_float4(c, c, -s, -s);
    } else if (tid == 34) {
        float s, c; __sincosf(0.5f * w[13], &s, &c);
        r2c4 = make_float4(c, c, -s, -s);
    } else if (tid == 35) {
        float s, c; __sincosf(w[15], &s, &c);
        w3c[0] = c; w3c[1] = -2.f * s;
    }
    __syncthreads();

    const ulonglong2* dRIp = reinterpret_cast<const ulonglong2*>(dRI);

    // ---- Stage A: evaluate the circuit at the 81 grid points ----
    if (tid < 81) {
        const float TH0 = 0.0f, TH1 = 2.0943951023931953f, TH2 = -2.0943951023931953f;
        int j1 = tid / 27, j2 = (tid / 9) % 3, j3 = (tid / 3) % 3, j4 = tid % 3;
        float th[3] = {TH0, TH1, TH2};
        float4 gx = make_float4(th[j1], th[j2], th[j3], th[j4]);
        float4 r = qbody(gx, l0c, dRIp, &r0c4, &r1c4, &r2c4, w3c);
        kf[tid * 4 + 0] = r.x;
        kf[tid * 4 + 1] = r.y;
        kf[tid * 4 + 2] = r.z;
        kf[tid * 4 + 3] = r.w;
    }
    __syncthreads();

    // ---- Stage B: per-qubit inverse interpolation transforms (in place) ----
    if (tid < 108) { int c = tid >> 2, o = tid & 3; xform3(kf, c * 12 + o, 4); }
    __syncthreads();
    if (tid < 108) { int g = tid / 12, r = tid % 12; xform3(kf, g * 36 + r, 12); }
    __syncthreads();
    if (tid < 108) { int g = tid / 36, r = tid % 36; xform3(kf, g * 108 + r, 36); }
    __syncthreads();
    if (tid < 108) { xform3(kf, tid, 108); }
    __syncthreads();

    unsigned kbase;
    asm("{ .reg .u64 t; cvta.to.shared.u64 t, %1; cvt.u32.u64 %0, t; }"
        : "=r"(kbase) : "l"(kf));

    // ---- Stage C: dual-sample main pass + dual-sample balanced tail ----
    unsigned bid = blockIdx.x;
    unsigned b0 = bid * (unsigned)TPB + tid;
    unsigned b1 = b0 + STRIDE;

    // tail: samples [378880, 524288), block i gets 197 (i<368) or 196 samples
    unsigned n = (bid < 368u) ? 197u : 196u;
    unsigned T0 = 2u * STRIDE + bid * 196u + min(bid, 368u);
    unsigned nA = (n + 1u) >> 1;                 // 99 or 98
    bool tactA = (unsigned)tid < nA;
    bool tactB = tactA && (nA + (unsigned)tid < n);
    unsigned ia = T0 + (unsigned)tid;
    unsigned ib = ia + nA;

    float4 xa = x[b0];
    float4 xb = x[b1];
    float4 xta = tactA ? x[ia] : xa;             // prefetched before heavy pass
    float4 xtb = tactB ? x[ib] : xta;

    float4 oa, ob;
    hbody2(xa, xb, kbase, oa, ob);
    out[b0] = oa;
    out[b1] = ob;

    if (tactA) {
        float4 o1, o2;
        hbody2(xta, xtb, kbase, o1, o2);
        out[ia] = o1;
        if (tactB) out[ib] = o2;
    }
}

extern "C" void kernel_launch(void* const* d_in, const int* in_sizes, int n_in,
                              void* d_out, int out_size) {
    const float4* x = (const float4*)d_in[0];
    const float*  w = (const float*)d_in[1];
    float4* out = (float4*)d_out;
    quantum_layer_kernel<<<GRID, TPB>>>(x, w, out);
}